// round 3
// baseline (speedup 1.0000x reference)
#include <cuda_runtime.h>
#include <stdint.h>

#define NN 100000
#define NE 1600000
#define DD 64
#define SCAN_B 1024
#define NBLK_SCAN ((NN + SCAN_B - 1) / SCAN_B)   // 98

// ---- scratch (__device__ globals; allocation-free per harness rules) ----
__device__ float g_deg[NN];
__device__ float g_dinv[NN];
__device__ int   g_cnt[NN];        // in-degree (no self-loop)
__device__ int   g_ptr[NN];        // CSR start offsets (exclusive scan of cnt)
__device__ int   g_wctr[NN];       // placement cursors
__device__ int   g_bsum[NBLK_SCAN];
__device__ int   g_erow[NE];       // CSR: source node per edge slot
__device__ float g_enrm[NE];       // CSR: norm coefficient per edge slot
__device__ float g_h[NN * DD];     // post-GEMM features (gather source)
__device__ float g_agg0[NN * DD];  // layer-1 aggregation result

// ---- init: deg=1 (self loop), cnt=0 ----
__global__ void k_init() {
    int i = blockIdx.x * blockDim.x + threadIdx.x;
    if (i < NN) { g_deg[i] = 1.0f; g_cnt[i] = 0; }
}

// ---- degree + in-count accumulation (adj is int32!) ----
__global__ void k_deg_acc(const int* __restrict__ adj,
                          const float* __restrict__ w) {
    int e = blockIdx.x * blockDim.x + threadIdx.x;
    if (e < NE) {
        int c = adj[NE + e];
        atomicAdd(&g_deg[c], w[e]);
        atomicAdd(&g_cnt[c], 1);
    }
}

__global__ void k_dinv() {
    int i = blockIdx.x * blockDim.x + threadIdx.x;
    if (i < NN) g_dinv[i] = rsqrtf(g_deg[i]);   // deg >= 1 always
}

// ---- exclusive scan of g_cnt -> g_ptr (3 kernels) ----
__global__ void k_scan1() {
    __shared__ int s[SCAN_B];
    int i = blockIdx.x * SCAN_B + threadIdx.x;
    int v = (i < NN) ? g_cnt[i] : 0;
    s[threadIdx.x] = v;
    __syncthreads();
#pragma unroll
    for (int off = 1; off < SCAN_B; off <<= 1) {
        int t = (threadIdx.x >= off) ? s[threadIdx.x - off] : 0;
        __syncthreads();
        s[threadIdx.x] += t;
        __syncthreads();
    }
    if (i < NN) g_ptr[i] = s[threadIdx.x] - v;          // block-local exclusive
    if (threadIdx.x == SCAN_B - 1) g_bsum[blockIdx.x] = s[SCAN_B - 1];
}

__global__ void k_scan2() {
    if (threadIdx.x == 0) {
        int acc = 0;
        for (int b = 0; b < NBLK_SCAN; b++) {
            int t = g_bsum[b]; g_bsum[b] = acc; acc += t;
        }
    }
}

__global__ void k_scan3() {
    int i = blockIdx.x * blockDim.x + threadIdx.x;
    if (i < NN) {
        int v = g_ptr[i] + g_bsum[i >> 10];
        g_ptr[i]  = v;
        g_wctr[i] = v;
    }
}

// ---- CSR placement: bin edges by destination, precompute norm ----
__global__ void k_place(const int* __restrict__ adj,
                        const float* __restrict__ w) {
    int e = blockIdx.x * blockDim.x + threadIdx.x;
    if (e < NE) {
        int r = adj[e];
        int c = adj[NE + e];
        int pos = atomicAdd(&g_wctr[c], 1);
        g_erow[pos] = r;
        g_enrm[pos] = g_dinv[r] * w[e] * g_dinv[c];
    }
}

// ---- fused GEMM: h = f(xin) @ W ----
// LAYER==1: xin = x input. LAYER==2: xin = g_agg0, f = relu(v + b1[d]).
template <int LAYER>
__global__ void __launch_bounds__(512)
k_gemm(const float* __restrict__ xin,
       const float* __restrict__ W,
       const float* __restrict__ bprev) {
    __shared__ float Ws[DD * DD];
    __shared__ float xs[8][DD];

    int d = threadIdx.x;          // 0..63
    int r = threadIdx.y;          // 0..7
    int t = r * DD + d;

#pragma unroll
    for (int i = 0; i < 8; i++) Ws[t + i * 512] = W[t + i * 512];

    int node = blockIdx.x * 8 + r;   // 12500 * 8 == 100000 exactly
    const float* src = (LAYER == 1) ? xin : g_agg0;
    float v = src[node * DD + d];
    if (LAYER == 2) v = fmaxf(v + bprev[d], 0.0f);
    xs[r][d] = v;
    __syncthreads();

    float acc = 0.0f;
#pragma unroll
    for (int k = 0; k < DD; k++)
        acc = fmaf(xs[r][k], Ws[k * DD + d], acc);

    g_h[node * DD + d] = acc;
}

// ---- gather aggregation: agg[c] = dinv[c]^2*h[c] + sum_e nrm[e]*h[row[e]] ----
// 64 threads per node (4 nodes per 256-thread block). No atomics.
template <int LAYER>
__global__ void __launch_bounds__(256)
k_agg(const float* __restrict__ b2, float* __restrict__ out) {
    int node = blockIdx.x * 4 + (threadIdx.x >> 6);  // 25000*4 == 100000 exactly
    int d = threadIdx.x & 63;

    int beg = g_ptr[node];
    int end = beg + g_cnt[node];

    float di = g_dinv[node];
    float acc = di * di * g_h[node * DD + d];        // self-loop term

    for (int j = beg; j < end; j++) {
        int   r  = g_erow[j];
        float nm = g_enrm[j];
        acc = fmaf(nm, g_h[r * DD + d], acc);
    }

    if (LAYER == 1) {
        g_agg0[node * DD + d] = acc;                 // bias+relu fused into GEMM2
    } else {
        out[node * DD + d] = fmaxf(acc + b2[d], 0.0f);
    }
}

extern "C" void kernel_launch(void* const* d_in, const int* in_sizes, int n_in,
                              void* d_out, int out_size) {
    const float* x   = (const float*)d_in[0];
    const int*   adj = (const int*)d_in[1];    // [2, NE] — int32 (JAX x64 disabled)
    const float* w   = (const float*)d_in[2];
    const float* W1  = (const float*)d_in[3];
    const float* b1  = (const float*)d_in[4];
    const float* W2  = (const float*)d_in[5];
    const float* b2  = (const float*)d_in[6];
    float* out = (float*)d_out;

    // ---- graph prep ----
    k_init<<<(NN + 255) / 256, 256>>>();
    k_deg_acc<<<(NE + 255) / 256, 256>>>(adj, w);
    k_dinv<<<(NN + 255) / 256, 256>>>();
    k_scan1<<<NBLK_SCAN, SCAN_B>>>();
    k_scan2<<<1, 32>>>();
    k_scan3<<<(NN + 255) / 256, 256>>>();
    k_place<<<(NE + 255) / 256, 256>>>(adj, w);

    dim3 gblk(64, 8);

    // ---- layer 1 ----
    k_gemm<1><<<NN / 8, gblk>>>(x, W1, nullptr);
    k_agg<1><<<NN / 4, 256>>>(nullptr, nullptr);

    // ---- layer 2 ----
    k_gemm<2><<<NN / 8, gblk>>>(nullptr, W2, b1);
    k_agg<2><<<NN / 4, 256>>>(b2, out);
}

// round 9
// speedup vs baseline: 1.9025x; 1.9025x over previous
#include <cuda_runtime.h>
#include <stdint.h>

#define NN 100000
#define NE 1600000
#define DD 64
#define SCAN_B 1024
#define NBLK_SCAN ((NN + SCAN_B - 1) / SCAN_B)   // 98

// ---- scratch (__device__ globals; allocation-free per harness rules) ----
__device__ float g_deg[NN];          // zeroed by k_dinv after use (replay-safe)
__device__ float g_dinv[NN];
__device__ int   g_cnt[NN];          // zeroed by k_scan1 after read (replay-safe)
__device__ int   g_ptr[NN + 1];      // CSR offsets (exclusive scan), ptr[NN]=NE
__device__ int   g_wctr[NN];         // placement cursors
__device__ int   g_bsum[128];
__device__ int   g_erow[NE];         // CSR: source node per edge slot
__device__ __align__(16) float g_enrm[NE];
__device__ __align__(16) float g_h[NN * DD];
__device__ __align__(16) float g_agg0[NN * DD];

// ---- degree + in-count accumulation (adj is int32) ----
__global__ void k_deg_acc(const int* __restrict__ adj,
                          const float* __restrict__ w) {
    int e = blockIdx.x * blockDim.x + threadIdx.x;
    if (e < NE) {
        int c = adj[NE + e];
        atomicAdd(&g_deg[c], w[e]);
        atomicAdd(&g_cnt[c], 1);
    }
}

// dinv = rsqrt(deg + 1 self-loop); reset deg for next graph replay
__global__ void k_dinv() {
    int i = blockIdx.x * blockDim.x + threadIdx.x;
    if (i < NN) {
        g_dinv[i] = rsqrtf(g_deg[i] + 1.0f);
        g_deg[i] = 0.0f;
    }
}

// ---- exclusive scan of g_cnt -> g_ptr ----
__global__ void k_scan1() {
    __shared__ int s[SCAN_B];
    int i = blockIdx.x * SCAN_B + threadIdx.x;
    int v = (i < NN) ? g_cnt[i] : 0;
    if (i < NN) g_cnt[i] = 0;                 // reset for next replay
    s[threadIdx.x] = v;
    __syncthreads();
#pragma unroll
    for (int off = 1; off < SCAN_B; off <<= 1) {
        int t = (threadIdx.x >= off) ? s[threadIdx.x - off] : 0;
        __syncthreads();
        s[threadIdx.x] += t;
        __syncthreads();
    }
    if (i < NN) g_ptr[i] = s[threadIdx.x] - v;          // block-local exclusive
    if (threadIdx.x == SCAN_B - 1) g_bsum[blockIdx.x] = s[SCAN_B - 1];
}

__global__ void k_scan2() {      // 128-thread Hillis-Steele over 98 block sums
    __shared__ int s[128];
    int i = threadIdx.x;
    int v = (i < NBLK_SCAN) ? g_bsum[i] : 0;
    s[i] = v;
    __syncthreads();
#pragma unroll
    for (int off = 1; off < 128; off <<= 1) {
        int t = (i >= off) ? s[i - off] : 0;
        __syncthreads();
        s[i] += t;
        __syncthreads();
    }
    if (i < NBLK_SCAN) g_bsum[i] = s[i] - v;  // exclusive
}

__global__ void k_scan3() {
    int i = blockIdx.x * blockDim.x + threadIdx.x;
    if (i < NN) {
        int v = g_ptr[i] + g_bsum[i >> 10];
        g_ptr[i]  = v;
        g_wctr[i] = v;
    }
    if (i == 0) g_ptr[NN] = NE;
}

// ---- CSR placement: bin edges by destination, precompute norm ----
__global__ void k_place(const int* __restrict__ adj,
                        const float* __restrict__ w) {
    int e = blockIdx.x * blockDim.x + threadIdx.x;
    if (e < NE) {
        int r = adj[e];
        int c = adj[NE + e];
        int pos = atomicAdd(&g_wctr[c], 1);
        g_erow[pos] = r;
        g_enrm[pos] = g_dinv[r] * w[e] * g_dinv[c];
    }
}

// ---- register-tiled GEMM: h = f(xin) @ W ----
// Block: 256 thr, 64-node tile. Thread (q,m): 4 d-cols (q*4..) x 4 nodes (m*4..).
// LAYER==1: xin = x. LAYER==2: xin = g_agg0, f = relu(v + b1[d]).
template <int LAYER>
__global__ void __launch_bounds__(256)
k_gemm(const float* __restrict__ xin,
       const float* __restrict__ W,
       const float* __restrict__ bprev) {
    __shared__ float Ws[DD * DD];
    __shared__ float xs[64][DD];

    int tid = threadIdx.x;
    int base = blockIdx.x * 64;

    // W load: 1024 float4 / 256 threads
    const float4* W4 = (const float4*)W;
    float4* Ws4 = (float4*)Ws;
#pragma unroll
    for (int i = 0; i < 4; i++) Ws4[tid + i * 256] = W4[tid + i * 256];

    // xs load: 64 rows x 16 float4 (clamped for the ragged last block)
    const float4* src4 = (LAYER == 1) ? (const float4*)xin : (const float4*)g_agg0;
    float4* xs4 = (float4*)&xs[0][0];
#pragma unroll
    for (int i = 0; i < 4; i++) {
        int idx = tid + i * 256;
        int n = idx >> 4;
        int gn = base + n;
        if (gn >= NN) gn = NN - 1;
        float4 v = src4[gn * 16 + (idx & 15)];
        if (LAYER == 2) {
            int d = (idx & 15) * 4;
            v.x = fmaxf(v.x + __ldg(bprev + d),     0.0f);
            v.y = fmaxf(v.y + __ldg(bprev + d + 1), 0.0f);
            v.z = fmaxf(v.z + __ldg(bprev + d + 2), 0.0f);
            v.w = fmaxf(v.w + __ldg(bprev + d + 3), 0.0f);
        }
        xs4[idx] = v;
    }
    __syncthreads();

    int q = tid & 15;     // d-quad
    int m = tid >> 4;     // node-quad

    float a0x=0,a0y=0,a0z=0,a0w=0, a1x=0,a1y=0,a1z=0,a1w=0;
    float a2x=0,a2y=0,a2z=0,a2w=0, a3x=0,a3y=0,a3z=0,a3w=0;

#pragma unroll
    for (int k = 0; k < DD; k += 2) {
        float4 w0 = *(const float4*)&Ws[k * DD + q * 4];
        float4 w1 = *(const float4*)&Ws[(k + 1) * DD + q * 4];
        float2 x0 = *(const float2*)&xs[m * 4 + 0][k];
        float2 x1 = *(const float2*)&xs[m * 4 + 1][k];
        float2 x2 = *(const float2*)&xs[m * 4 + 2][k];
        float2 x3 = *(const float2*)&xs[m * 4 + 3][k];

        a0x=fmaf(x0.x,w0.x,a0x); a0y=fmaf(x0.x,w0.y,a0y); a0z=fmaf(x0.x,w0.z,a0z); a0w=fmaf(x0.x,w0.w,a0w);
        a1x=fmaf(x1.x,w0.x,a1x); a1y=fmaf(x1.x,w0.y,a1y); a1z=fmaf(x1.x,w0.z,a1z); a1w=fmaf(x1.x,w0.w,a1w);
        a2x=fmaf(x2.x,w0.x,a2x); a2y=fmaf(x2.x,w0.y,a2y); a2z=fmaf(x2.x,w0.z,a2z); a2w=fmaf(x2.x,w0.w,a2w);
        a3x=fmaf(x3.x,w0.x,a3x); a3y=fmaf(x3.x,w0.y,a3y); a3z=fmaf(x3.x,w0.z,a3z); a3w=fmaf(x3.x,w0.w,a3w);

        a0x=fmaf(x0.y,w1.x,a0x); a0y=fmaf(x0.y,w1.y,a0y); a0z=fmaf(x0.y,w1.z,a0z); a0w=fmaf(x0.y,w1.w,a0w);
        a1x=fmaf(x1.y,w1.x,a1x); a1y=fmaf(x1.y,w1.y,a1y); a1z=fmaf(x1.y,w1.z,a1z); a1w=fmaf(x1.y,w1.w,a1w);
        a2x=fmaf(x2.y,w1.x,a2x); a2y=fmaf(x2.y,w1.y,a2y); a2z=fmaf(x2.y,w1.z,a2z); a2w=fmaf(x2.y,w1.w,a2w);
        a3x=fmaf(x3.y,w1.x,a3x); a3y=fmaf(x3.y,w1.y,a3y); a3z=fmaf(x3.y,w1.z,a3z); a3w=fmaf(x3.y,w1.w,a3w);
    }

    int n0 = base + m * 4;
    if (n0 + 0 < NN) *(float4*)&g_h[(n0+0)*DD + q*4] = make_float4(a0x,a0y,a0z,a0w);
    if (n0 + 1 < NN) *(float4*)&g_h[(n0+1)*DD + q*4] = make_float4(a1x,a1y,a1z,a1w);
    if (n0 + 2 < NN) *(float4*)&g_h[(n0+2)*DD + q*4] = make_float4(a2x,a2y,a2z,a2w);
    if (n0 + 3 < NN) *(float4*)&g_h[(n0+3)*DD + q*4] = make_float4(a3x,a3y,a3z,a3w);
}

// ---- gather aggregation: 16 threads/node, float4, 2-edge unroll ----
template <int LAYER>
__global__ void __launch_bounds__(256)
k_agg(const float* __restrict__ bias, float* __restrict__ out) {
    int node = blockIdx.x * 16 + (threadIdx.x >> 4);   // 6250*16 == 100000
    int lane = threadIdx.x & 15;
    const float4* h4 = (const float4*)g_h;

    int beg = g_ptr[node];
    int end = g_ptr[node + 1];

    float di = g_dinv[node];
    float s = di * di;
    float4 sv = h4[node * 16 + lane];
    float4 a0 = make_float4(s * sv.x, s * sv.y, s * sv.z, s * sv.w);
    float4 a1 = make_float4(0.f, 0.f, 0.f, 0.f);

    int j = beg;
    for (; j + 2 <= end; j += 2) {
        int   r0 = __ldg(g_erow + j);     float n0 = __ldg(g_enrm + j);
        int   r1 = __ldg(g_erow + j + 1); float n1 = __ldg(g_enrm + j + 1);
        float4 v0 = h4[r0 * 16 + lane];
        float4 v1 = h4[r1 * 16 + lane];
        a0.x = fmaf(n0, v0.x, a0.x); a0.y = fmaf(n0, v0.y, a0.y);
        a0.z = fmaf(n0, v0.z, a0.z); a0.w = fmaf(n0, v0.w, a0.w);
        a1.x = fmaf(n1, v1.x, a1.x); a1.y = fmaf(n1, v1.y, a1.y);
        a1.z = fmaf(n1, v1.z, a1.z); a1.w = fmaf(n1, v1.w, a1.w);
    }
    if (j < end) {
        int r = __ldg(g_erow + j); float nm = __ldg(g_enrm + j);
        float4 v = h4[r * 16 + lane];
        a0.x = fmaf(nm, v.x, a0.x); a0.y = fmaf(nm, v.y, a0.y);
        a0.z = fmaf(nm, v.z, a0.z); a0.w = fmaf(nm, v.w, a0.w);
    }
    float4 res = make_float4(a0.x + a1.x, a0.y + a1.y, a0.z + a1.z, a0.w + a1.w);

    if (LAYER == 1) {
        *(float4*)&g_agg0[node * DD + lane * 4] = res;   // bias+relu fused into GEMM2
    } else {
        int d = lane * 4;
        res.x = fmaxf(res.x + __ldg(bias + d),     0.0f);
        res.y = fmaxf(res.y + __ldg(bias + d + 1), 0.0f);
        res.z = fmaxf(res.z + __ldg(bias + d + 2), 0.0f);
        res.w = fmaxf(res.w + __ldg(bias + d + 3), 0.0f);
        *(float4*)&out[node * DD + d] = res;
    }
}

extern "C" void kernel_launch(void* const* d_in, const int* in_sizes, int n_in,
                              void* d_out, int out_size) {
    const float* x   = (const float*)d_in[0];
    const int*   adj = (const int*)d_in[1];    // [2, NE] int32
    const float* w   = (const float*)d_in[2];
    const float* W1  = (const float*)d_in[3];
    const float* b1  = (const float*)d_in[4];
    const float* W2  = (const float*)d_in[5];
    const float* b2  = (const float*)d_in[6];
    float* out = (float*)d_out;

    // ---- graph prep ----
    k_deg_acc<<<(NE + 255) / 256, 256>>>(adj, w);
    k_dinv<<<(NN + 255) / 256, 256>>>();
    k_scan1<<<NBLK_SCAN, SCAN_B>>>();
    k_scan2<<<1, 128>>>();
    k_scan3<<<(NN + 255) / 256, 256>>>();
    k_place<<<(NE + 255) / 256, 256>>>(adj, w);

    const int gemm_blocks = (NN + 63) / 64;   // 1563

    // ---- layer 1 ----
    k_gemm<1><<<gemm_blocks, 256>>>(x, W1, nullptr);
    k_agg<1><<<NN / 16, 256>>>(nullptr, nullptr);

    // ---- layer 2 ----
    k_gemm<2><<<gemm_blocks, 256>>>(nullptr, W2, b1);
    k_agg<2><<<NN / 16, 256>>>(b2, out);
}

// round 10
// speedup vs baseline: 2.0088x; 1.0559x over previous
#include <cuda_runtime.h>
#include <stdint.h>

#define NN 100000
#define NE 1600000
#define DD 64
#define SCAN_B 1024
#define NBLK_SCAN ((NN + SCAN_B - 1) / SCAN_B)   // 98

// ---- scratch (__device__ globals; allocation-free per harness rules) ----
__device__ float g_deg[NN];          // zeroed after use (replay-safe)
__device__ float g_dinv[NN];
__device__ int   g_cnt[NN];          // zeroed by k_scan1 after read (replay-safe)
__device__ int   g_ptr[NN + 1];      // CSR offsets (exclusive scan), ptr[NN]=NE
__device__ int   g_wctr[NN];         // placement cursors
__device__ int   g_bsum[128];
__device__ __align__(16) int2  g_edge[NE];   // CSR: {src row, norm-as-bits} records
__device__ __align__(16) float g_h[NN * DD];
__device__ __align__(16) float g_agg0[NN * DD];

// ---- degree + in-count accumulation (adj is int32) ----
__global__ void k_deg_acc(const int* __restrict__ adj,
                          const float* __restrict__ w) {
    int e = blockIdx.x * blockDim.x + threadIdx.x;
    if (e < NE) {
        int c = adj[NE + e];
        atomicAdd(&g_deg[c], w[e]);
        atomicAdd(&g_cnt[c], 1);
    }
}

// ---- scan1: block-local exclusive scan of cnt + dinv compute (fused) ----
__global__ void k_scan1() {
    __shared__ int s[SCAN_B];
    int i = blockIdx.x * SCAN_B + threadIdx.x;
    int v = (i < NN) ? g_cnt[i] : 0;
    if (i < NN) {
        g_cnt[i] = 0;                              // reset for next replay
        g_dinv[i] = rsqrtf(g_deg[i] + 1.0f);       // +1 self-loop
        g_deg[i] = 0.0f;                           // reset for next replay
    }
    s[threadIdx.x] = v;
    __syncthreads();
#pragma unroll
    for (int off = 1; off < SCAN_B; off <<= 1) {
        int t = (threadIdx.x >= off) ? s[threadIdx.x - off] : 0;
        __syncthreads();
        s[threadIdx.x] += t;
        __syncthreads();
    }
    if (i < NN) g_ptr[i] = s[threadIdx.x] - v;          // block-local exclusive
    if (threadIdx.x == SCAN_B - 1) g_bsum[blockIdx.x] = s[SCAN_B - 1];
}

__global__ void k_scan2() {      // 128-thread Hillis-Steele over 98 block sums
    __shared__ int s[128];
    int i = threadIdx.x;
    int v = (i < NBLK_SCAN) ? g_bsum[i] : 0;
    s[i] = v;
    __syncthreads();
#pragma unroll
    for (int off = 1; off < 128; off <<= 1) {
        int t = (i >= off) ? s[i - off] : 0;
        __syncthreads();
        s[i] += t;
        __syncthreads();
    }
    if (i < NBLK_SCAN) g_bsum[i] = s[i] - v;  // exclusive
}

__global__ void k_scan3() {
    int i = blockIdx.x * blockDim.x + threadIdx.x;
    if (i < NN) {
        int v = g_ptr[i] + g_bsum[i >> 10];
        g_ptr[i]  = v;
        g_wctr[i] = v;
    }
    if (i == 0) g_ptr[NN] = NE;
}

// ---- CSR placement: bin edges by destination, one 8B record per edge ----
__global__ void k_place(const int* __restrict__ adj,
                        const float* __restrict__ w) {
    int e = blockIdx.x * blockDim.x + threadIdx.x;
    if (e < NE) {
        int r = adj[e];
        int c = adj[NE + e];
        float nm = g_dinv[r] * w[e] * g_dinv[c];
        int pos = atomicAdd(&g_wctr[c], 1);
        g_edge[pos] = make_int2(r, __float_as_int(nm));
    }
}

// ---- register-tiled GEMM: h = f(xin) @ W ----
// Block: 256 thr, 64-node tile. Thread (q,m): 4 d-cols (q*4..) x 4 nodes (m*4..).
// LAYER==1: xin = x. LAYER==2: xin = g_agg0, f = relu(v + b1[d]).
template <int LAYER>
__global__ void __launch_bounds__(256)
k_gemm(const float* __restrict__ xin,
       const float* __restrict__ W,
       const float* __restrict__ bprev) {
    __shared__ float Ws[DD * DD];
    __shared__ float xs[64][DD];

    int tid = threadIdx.x;
    int base = blockIdx.x * 64;

    // W load: 1024 float4 / 256 threads
    const float4* W4 = (const float4*)W;
    float4* Ws4 = (float4*)Ws;
#pragma unroll
    for (int i = 0; i < 4; i++) Ws4[tid + i * 256] = W4[tid + i * 256];

    // xs load: 64 rows x 16 float4 (clamped for the ragged last block)
    const float4* src4 = (LAYER == 1) ? (const float4*)xin : (const float4*)g_agg0;
    float4* xs4 = (float4*)&xs[0][0];
#pragma unroll
    for (int i = 0; i < 4; i++) {
        int idx = tid + i * 256;
        int n = idx >> 4;
        int gn = base + n;
        if (gn >= NN) gn = NN - 1;
        float4 v = src4[gn * 16 + (idx & 15)];
        if (LAYER == 2) {
            int d = (idx & 15) * 4;
            v.x = fmaxf(v.x + __ldg(bprev + d),     0.0f);
            v.y = fmaxf(v.y + __ldg(bprev + d + 1), 0.0f);
            v.z = fmaxf(v.z + __ldg(bprev + d + 2), 0.0f);
            v.w = fmaxf(v.w + __ldg(bprev + d + 3), 0.0f);
        }
        xs4[idx] = v;
    }
    __syncthreads();

    int q = tid & 15;     // d-quad
    int m = tid >> 4;     // node-quad

    float a0x=0,a0y=0,a0z=0,a0w=0, a1x=0,a1y=0,a1z=0,a1w=0;
    float a2x=0,a2y=0,a2z=0,a2w=0, a3x=0,a3y=0,a3z=0,a3w=0;

#pragma unroll
    for (int k = 0; k < DD; k += 2) {
        float4 w0 = *(const float4*)&Ws[k * DD + q * 4];
        float4 w1 = *(const float4*)&Ws[(k + 1) * DD + q * 4];
        float2 x0 = *(const float2*)&xs[m * 4 + 0][k];
        float2 x1 = *(const float2*)&xs[m * 4 + 1][k];
        float2 x2 = *(const float2*)&xs[m * 4 + 2][k];
        float2 x3 = *(const float2*)&xs[m * 4 + 3][k];

        a0x=fmaf(x0.x,w0.x,a0x); a0y=fmaf(x0.x,w0.y,a0y); a0z=fmaf(x0.x,w0.z,a0z); a0w=fmaf(x0.x,w0.w,a0w);
        a1x=fmaf(x1.x,w0.x,a1x); a1y=fmaf(x1.x,w0.y,a1y); a1z=fmaf(x1.x,w0.z,a1z); a1w=fmaf(x1.x,w0.w,a1w);
        a2x=fmaf(x2.x,w0.x,a2x); a2y=fmaf(x2.x,w0.y,a2y); a2z=fmaf(x2.x,w0.z,a2z); a2w=fmaf(x2.x,w0.w,a2w);
        a3x=fmaf(x3.x,w0.x,a3x); a3y=fmaf(x3.x,w0.y,a3y); a3z=fmaf(x3.x,w0.z,a3z); a3w=fmaf(x3.x,w0.w,a3w);

        a0x=fmaf(x0.y,w1.x,a0x); a0y=fmaf(x0.y,w1.y,a0y); a0z=fmaf(x0.y,w1.z,a0z); a0w=fmaf(x0.y,w1.w,a0w);
        a1x=fmaf(x1.y,w1.x,a1x); a1y=fmaf(x1.y,w1.y,a1y); a1z=fmaf(x1.y,w1.z,a1z); a1w=fmaf(x1.y,w1.w,a1w);
        a2x=fmaf(x2.y,w1.x,a2x); a2y=fmaf(x2.y,w1.y,a2y); a2z=fmaf(x2.y,w1.z,a2z); a2w=fmaf(x2.y,w1.w,a2w);
        a3x=fmaf(x3.y,w1.x,a3x); a3y=fmaf(x3.y,w1.y,a3y); a3z=fmaf(x3.y,w1.z,a3z); a3w=fmaf(x3.y,w1.w,a3w);
    }

    int n0 = base + m * 4;
    if (n0 + 0 < NN) *(float4*)&g_h[(n0+0)*DD + q*4] = make_float4(a0x,a0y,a0z,a0w);
    if (n0 + 1 < NN) *(float4*)&g_h[(n0+1)*DD + q*4] = make_float4(a1x,a1y,a1z,a1w);
    if (n0 + 2 < NN) *(float4*)&g_h[(n0+2)*DD + q*4] = make_float4(a2x,a2y,a2z,a2w);
    if (n0 + 3 < NN) *(float4*)&g_h[(n0+3)*DD + q*4] = make_float4(a3x,a3y,a3z,a3w);
}

// ---- gather aggregation: 16 threads/node, float4, 2-edge unroll ----
template <int LAYER>
__global__ void __launch_bounds__(256)
k_agg(const float* __restrict__ bias, float* __restrict__ out) {
    int node = blockIdx.x * 16 + (threadIdx.x >> 4);   // 6250*16 == 100000
    int lane = threadIdx.x & 15;
    const float4* h4 = (const float4*)g_h;

    int beg = g_ptr[node];
    int end = g_ptr[node + 1];

    float di = g_dinv[node];
    float s = di * di;
    float4 sv = h4[node * 16 + lane];
    float4 a0 = make_float4(s * sv.x, s * sv.y, s * sv.z, s * sv.w);
    float4 a1 = make_float4(0.f, 0.f, 0.f, 0.f);

    int j = beg;
    for (; j + 2 <= end; j += 2) {
        int2 e0 = __ldg(g_edge + j);
        int2 e1 = __ldg(g_edge + j + 1);
        float n0 = __int_as_float(e0.y);
        float n1 = __int_as_float(e1.y);
        float4 v0 = h4[e0.x * 16 + lane];
        float4 v1 = h4[e1.x * 16 + lane];
        a0.x = fmaf(n0, v0.x, a0.x); a0.y = fmaf(n0, v0.y, a0.y);
        a0.z = fmaf(n0, v0.z, a0.z); a0.w = fmaf(n0, v0.w, a0.w);
        a1.x = fmaf(n1, v1.x, a1.x); a1.y = fmaf(n1, v1.y, a1.y);
        a1.z = fmaf(n1, v1.z, a1.z); a1.w = fmaf(n1, v1.w, a1.w);
    }
    if (j < end) {
        int2 e0 = __ldg(g_edge + j);
        float nm = __int_as_float(e0.y);
        float4 v = h4[e0.x * 16 + lane];
        a0.x = fmaf(nm, v.x, a0.x); a0.y = fmaf(nm, v.y, a0.y);
        a0.z = fmaf(nm, v.z, a0.z); a0.w = fmaf(nm, v.w, a0.w);
    }
    float4 res = make_float4(a0.x + a1.x, a0.y + a1.y, a0.z + a1.z, a0.w + a1.w);

    if (LAYER == 1) {
        *(float4*)&g_agg0[node * DD + lane * 4] = res;   // bias+relu fused into GEMM2
    } else {
        int d = lane * 4;
        res.x = fmaxf(res.x + __ldg(bias + d),     0.0f);
        res.y = fmaxf(res.y + __ldg(bias + d + 1), 0.0f);
        res.z = fmaxf(res.z + __ldg(bias + d + 2), 0.0f);
        res.w = fmaxf(res.w + __ldg(bias + d + 3), 0.0f);
        *(float4*)&out[node * DD + d] = res;
    }
}

extern "C" void kernel_launch(void* const* d_in, const int* in_sizes, int n_in,
                              void* d_out, int out_size) {
    const float* x   = (const float*)d_in[0];
    const int*   adj = (const int*)d_in[1];    // [2, NE] int32
    const float* w   = (const float*)d_in[2];
    const float* W1  = (const float*)d_in[3];
    const float* b1  = (const float*)d_in[4];
    const float* W2  = (const float*)d_in[5];
    const float* b2  = (const float*)d_in[6];
    float* out = (float*)d_out;

    // ---- graph prep ----
    k_deg_acc<<<(NE + 255) / 256, 256>>>(adj, w);
    k_scan1<<<NBLK_SCAN, SCAN_B>>>();          // scan + dinv fused
    k_scan2<<<1, 128>>>();
    k_scan3<<<(NN + 255) / 256, 256>>>();
    k_place<<<(NE + 255) / 256, 256>>>(adj, w);

    const int gemm_blocks = (NN + 63) / 64;   // 1563

    // ---- layer 1 ----
    k_gemm<1><<<gemm_blocks, 256>>>(x, W1, nullptr);
    k_agg<1><<<NN / 16, 256>>>(nullptr, nullptr);

    // ---- layer 2 ----
    k_gemm<2><<<gemm_blocks, 256>>>(nullptr, W2, b1);
    k_agg<2><<<NN / 16, 256>>>(b2, out);
}

// round 11
// speedup vs baseline: 2.0114x; 1.0013x over previous
#include <cuda_runtime.h>
#include <stdint.h>

#define NN 100000
#define NE 1600000
#define DD 64
#define SCAN_B 1024
#define NBLK_SCAN ((NN + SCAN_B - 1) / SCAN_B)   // 98

// ---- scratch (__device__ globals; allocation-free per harness rules) ----
__device__ float g_deg[NN];          // zeroed after use (replay-safe)
__device__ float g_dinv[NN];
__device__ int   g_cnt[NN];          // zeroed by k_scan1 after read (replay-safe)
__device__ int   g_ptr[NN + 1];      // CSR offsets (exclusive scan), ptr[NN]=NE
__device__ int   g_wctr[NN];         // placement cursors
__device__ int   g_bsum[128];
__device__ __align__(16) int2  g_edge[NE];   // CSR: {src row, norm-as-bits} records
__device__ __align__(16) float g_h[NN * DD];
__device__ __align__(16) float g_agg0[NN * DD];

// ---- degree + in-count accumulation (adj is int32) ----
__global__ void k_deg_acc(const int* __restrict__ adj,
                          const float* __restrict__ w) {
    int e = blockIdx.x * blockDim.x + threadIdx.x;
    if (e < NE) {
        int c = adj[NE + e];
        atomicAdd(&g_deg[c], w[e]);
        atomicAdd(&g_cnt[c], 1);
    }
}

// ---- scan1: block-local exclusive scan of cnt + dinv compute (fused) ----
__global__ void k_scan1() {
    __shared__ int s[SCAN_B];
    int i = blockIdx.x * SCAN_B + threadIdx.x;
    int v = (i < NN) ? g_cnt[i] : 0;
    if (i < NN) {
        g_cnt[i] = 0;                              // reset for next replay
        g_dinv[i] = rsqrtf(g_deg[i] + 1.0f);       // +1 self-loop
        g_deg[i] = 0.0f;                           // reset for next replay
    }
    s[threadIdx.x] = v;
    __syncthreads();
#pragma unroll
    for (int off = 1; off < SCAN_B; off <<= 1) {
        int t = (threadIdx.x >= off) ? s[threadIdx.x - off] : 0;
        __syncthreads();
        s[threadIdx.x] += t;
        __syncthreads();
    }
    if (i < NN) g_ptr[i] = s[threadIdx.x] - v;          // block-local exclusive
    if (threadIdx.x == SCAN_B - 1) g_bsum[blockIdx.x] = s[SCAN_B - 1];
}

__global__ void k_scan2() {      // 128-thread Hillis-Steele over 98 block sums
    __shared__ int s[128];
    int i = threadIdx.x;
    int v = (i < NBLK_SCAN) ? g_bsum[i] : 0;
    s[i] = v;
    __syncthreads();
#pragma unroll
    for (int off = 1; off < 128; off <<= 1) {
        int t = (i >= off) ? s[i - off] : 0;
        __syncthreads();
        s[i] += t;
        __syncthreads();
    }
    if (i < NBLK_SCAN) g_bsum[i] = s[i] - v;  // exclusive
}

__global__ void k_scan3() {
    int i = blockIdx.x * blockDim.x + threadIdx.x;
    if (i < NN) {
        int v = g_ptr[i] + g_bsum[i >> 10];
        g_ptr[i]  = v;
        g_wctr[i] = v;
    }
    if (i == 0) g_ptr[NN] = NE;
}

// ---- CSR placement: bin edges by destination, one 8B record per edge ----
__global__ void k_place(const int* __restrict__ adj,
                        const float* __restrict__ w) {
    int e = blockIdx.x * blockDim.x + threadIdx.x;
    if (e < NE) {
        int r = adj[e];
        int c = adj[NE + e];
        float nm = g_dinv[r] * w[e] * g_dinv[c];
        int pos = atomicAdd(&g_wctr[c], 1);
        g_edge[pos] = make_int2(r, __float_as_int(nm));
    }
}

// ---- register-tiled GEMM: h = f(xin) @ W ----
// Block: 256 thr, 64-node tile. Thread (q,m): 4 d-cols (q*4..) x 4 nodes (m*4..).
// LAYER==1: xin = x. LAYER==2: xin = g_agg0, f = relu(v + b1[d]).
template <int LAYER>
__global__ void __launch_bounds__(256)
k_gemm(const float* __restrict__ xin,
       const float* __restrict__ W,
       const float* __restrict__ bprev) {
    __shared__ float Ws[DD * DD];
    __shared__ float xs[64][DD];

    int tid = threadIdx.x;
    int base = blockIdx.x * 64;

    // W load: 1024 float4 / 256 threads
    const float4* W4 = (const float4*)W;
    float4* Ws4 = (float4*)Ws;
#pragma unroll
    for (int i = 0; i < 4; i++) Ws4[tid + i * 256] = W4[tid + i * 256];

    // xs load: 64 rows x 16 float4 (clamped for the ragged last block)
    const float4* src4 = (LAYER == 1) ? (const float4*)xin : (const float4*)g_agg0;
    float4* xs4 = (float4*)&xs[0][0];
#pragma unroll
    for (int i = 0; i < 4; i++) {
        int idx = tid + i * 256;
        int n = idx >> 4;
        int gn = base + n;
        if (gn >= NN) gn = NN - 1;
        float4 v = src4[gn * 16 + (idx & 15)];
        if (LAYER == 2) {
            int d = (idx & 15) * 4;
            v.x = fmaxf(v.x + __ldg(bprev + d),     0.0f);
            v.y = fmaxf(v.y + __ldg(bprev + d + 1), 0.0f);
            v.z = fmaxf(v.z + __ldg(bprev + d + 2), 0.0f);
            v.w = fmaxf(v.w + __ldg(bprev + d + 3), 0.0f);
        }
        xs4[idx] = v;
    }
    __syncthreads();

    int q = tid & 15;     // d-quad
    int m = tid >> 4;     // node-quad

    float a0x=0,a0y=0,a0z=0,a0w=0, a1x=0,a1y=0,a1z=0,a1w=0;
    float a2x=0,a2y=0,a2z=0,a2w=0, a3x=0,a3y=0,a3z=0,a3w=0;

#pragma unroll
    for (int k = 0; k < DD; k += 2) {
        float4 w0 = *(const float4*)&Ws[k * DD + q * 4];
        float4 w1 = *(const float4*)&Ws[(k + 1) * DD + q * 4];
        float2 x0 = *(const float2*)&xs[m * 4 + 0][k];
        float2 x1 = *(const float2*)&xs[m * 4 + 1][k];
        float2 x2 = *(const float2*)&xs[m * 4 + 2][k];
        float2 x3 = *(const float2*)&xs[m * 4 + 3][k];

        a0x=fmaf(x0.x,w0.x,a0x); a0y=fmaf(x0.x,w0.y,a0y); a0z=fmaf(x0.x,w0.z,a0z); a0w=fmaf(x0.x,w0.w,a0w);
        a1x=fmaf(x1.x,w0.x,a1x); a1y=fmaf(x1.x,w0.y,a1y); a1z=fmaf(x1.x,w0.z,a1z); a1w=fmaf(x1.x,w0.w,a1w);
        a2x=fmaf(x2.x,w0.x,a2x); a2y=fmaf(x2.x,w0.y,a2y); a2z=fmaf(x2.x,w0.z,a2z); a2w=fmaf(x2.x,w0.w,a2w);
        a3x=fmaf(x3.x,w0.x,a3x); a3y=fmaf(x3.x,w0.y,a3y); a3z=fmaf(x3.x,w0.z,a3z); a3w=fmaf(x3.x,w0.w,a3w);

        a0x=fmaf(x0.y,w1.x,a0x); a0y=fmaf(x0.y,w1.y,a0y); a0z=fmaf(x0.y,w1.z,a0z); a0w=fmaf(x0.y,w1.w,a0w);
        a1x=fmaf(x1.y,w1.x,a1x); a1y=fmaf(x1.y,w1.y,a1y); a1z=fmaf(x1.y,w1.z,a1z); a1w=fmaf(x1.y,w1.w,a1w);
        a2x=fmaf(x2.y,w1.x,a2x); a2y=fmaf(x2.y,w1.y,a2y); a2z=fmaf(x2.y,w1.z,a2z); a2w=fmaf(x2.y,w1.w,a2w);
        a3x=fmaf(x3.y,w1.x,a3x); a3y=fmaf(x3.y,w1.y,a3y); a3z=fmaf(x3.y,w1.z,a3z); a3w=fmaf(x3.y,w1.w,a3w);
    }

    int n0 = base + m * 4;
    if (n0 + 0 < NN) *(float4*)&g_h[(n0+0)*DD + q*4] = make_float4(a0x,a0y,a0z,a0w);
    if (n0 + 1 < NN) *(float4*)&g_h[(n0+1)*DD + q*4] = make_float4(a1x,a1y,a1z,a1w);
    if (n0 + 2 < NN) *(float4*)&g_h[(n0+2)*DD + q*4] = make_float4(a2x,a2y,a2z,a2w);
    if (n0 + 3 < NN) *(float4*)&g_h[(n0+3)*DD + q*4] = make_float4(a3x,a3y,a3z,a3w);
}

// ---- gather aggregation: 16 threads/node, float4, 2-edge unroll ----
template <int LAYER>
__global__ void __launch_bounds__(256)
k_agg(const float* __restrict__ bias, float* __restrict__ out) {
    int node = blockIdx.x * 16 + (threadIdx.x >> 4);   // 6250*16 == 100000
    int lane = threadIdx.x & 15;
    const float4* h4 = (const float4*)g_h;

    int beg = g_ptr[node];
    int end = g_ptr[node + 1];

    float di = g_dinv[node];
    float s = di * di;
    float4 sv = h4[node * 16 + lane];
    float4 a0 = make_float4(s * sv.x, s * sv.y, s * sv.z, s * sv.w);
    float4 a1 = make_float4(0.f, 0.f, 0.f, 0.f);

    int j = beg;
    for (; j + 2 <= end; j += 2) {
        int2 e0 = __ldg(g_edge + j);
        int2 e1 = __ldg(g_edge + j + 1);
        float n0 = __int_as_float(e0.y);
        float n1 = __int_as_float(e1.y);
        float4 v0 = h4[e0.x * 16 + lane];
        float4 v1 = h4[e1.x * 16 + lane];
        a0.x = fmaf(n0, v0.x, a0.x); a0.y = fmaf(n0, v0.y, a0.y);
        a0.z = fmaf(n0, v0.z, a0.z); a0.w = fmaf(n0, v0.w, a0.w);
        a1.x = fmaf(n1, v1.x, a1.x); a1.y = fmaf(n1, v1.y, a1.y);
        a1.z = fmaf(n1, v1.z, a1.z); a1.w = fmaf(n1, v1.w, a1.w);
    }
    if (j < end) {
        int2 e0 = __ldg(g_edge + j);
        float nm = __int_as_float(e0.y);
        float4 v = h4[e0.x * 16 + lane];
        a0.x = fmaf(nm, v.x, a0.x); a0.y = fmaf(nm, v.y, a0.y);
        a0.z = fmaf(nm, v.z, a0.z); a0.w = fmaf(nm, v.w, a0.w);
    }
    float4 res = make_float4(a0.x + a1.x, a0.y + a1.y, a0.z + a1.z, a0.w + a1.w);

    if (LAYER == 1) {
        *(float4*)&g_agg0[node * DD + lane * 4] = res;   // bias+relu fused into GEMM2
    } else {
        int d = lane * 4;
        res.x = fmaxf(res.x + __ldg(bias + d),     0.0f);
        res.y = fmaxf(res.y + __ldg(bias + d + 1), 0.0f);
        res.z = fmaxf(res.z + __ldg(bias + d + 2), 0.0f);
        res.w = fmaxf(res.w + __ldg(bias + d + 3), 0.0f);
        *(float4*)&out[node * DD + d] = res;
    }
}

extern "C" void kernel_launch(void* const* d_in, const int* in_sizes, int n_in,
                              void* d_out, int out_size) {
    const float* x   = (const float*)d_in[0];
    const int*   adj = (const int*)d_in[1];    // [2, NE] int32
    const float* w   = (const float*)d_in[2];
    const float* W1  = (const float*)d_in[3];
    const float* b1  = (const float*)d_in[4];
    const float* W2  = (const float*)d_in[5];
    const float* b2  = (const float*)d_in[6];
    float* out = (float*)d_out;

    // Lazy one-time stream/event creation. First kernel_launch call is the
    // (uncaptured) correctness run, so no capture-time resource creation.
    static cudaStream_t s2 = nullptr;
    static cudaEvent_t evFork = nullptr, evGemm1 = nullptr;
    if (!s2) {
        cudaStreamCreate(&s2);
        cudaEventCreateWithFlags(&evFork,  cudaEventDisableTiming);
        cudaEventCreateWithFlags(&evGemm1, cudaEventDisableTiming);
    }

    const int gemm_blocks = (NN + 63) / 64;   // 1563

    // ---- fork: gemm1 (only needs x, W1) runs concurrent with graph prep ----
    cudaEventRecord(evFork, 0);
    cudaStreamWaitEvent(s2, evFork, 0);
    k_gemm<1><<<gemm_blocks, 256, 0, s2>>>(x, W1, nullptr);
    cudaEventRecord(evGemm1, s2);

    // ---- graph prep (default stream) ----
    k_deg_acc<<<(NE + 255) / 256, 256>>>(adj, w);
    k_scan1<<<NBLK_SCAN, SCAN_B>>>();          // scan + dinv fused
    k_scan2<<<1, 128>>>();
    k_scan3<<<(NN + 255) / 256, 256>>>();
    k_place<<<(NE + 255) / 256, 256>>>(adj, w);

    // ---- join: agg1 needs both place and gemm1 ----
    cudaStreamWaitEvent(0, evGemm1, 0);
    k_agg<1><<<NN / 16, 256>>>(nullptr, nullptr);

    // ---- layer 2 ----
    k_gemm<2><<<gemm_blocks, 256>>>(nullptr, W2, b1);
    k_agg<2><<<NN / 16, 256>>>(b2, out);
}